// round 1
// baseline (speedup 1.0000x reference)
#include <cuda_runtime.h>
#include <math.h>

#define T_STEPS 2048
#define L 1024
#define NB 128          // persistent blocks (<= 148 SMs -> all co-resident)
#define JB 8            // columns per block (NB*JB == L)
#define NT 256          // threads per block (8 warps; warp w owns column jb+w)
#define LOG2E_F 1.4426950408889634f

// Persistent scratch (device globals: no runtime allocation)
__device__ float g_a[2][L];      // exp-domain scores, depth-2 ring
__device__ int   g_seq[NB];      // monotonic per-block sequence flags
__device__ float g_gold;

__device__ __forceinline__ int ld_acquire(const int* p) {
    int v;
    asm volatile("ld.acquire.gpu.s32 %0, [%1];" : "=r"(v) : "l"(p) : "memory");
    return v;
}
__device__ __forceinline__ void st_release(int* p, int v) {
    asm volatile("st.release.gpu.s32 [%0], %1;" :: "l"(p), "r"(v) : "memory");
}

// ---------------------------------------------------------------------------
// Prep: reset flags + compute gold path score
// ---------------------------------------------------------------------------
__global__ void crf_prep_kernel(const float* __restrict__ feats,
                                const float* __restrict__ transfer,
                                const int*   __restrict__ target) {
    int tid = threadIdx.x;
    if (tid < NB) g_seq[tid] = 0;

    float s = 0.f;
    for (int t = tid; t < T_STEPS; t += NT) {
        int lab = target[t];
        s += feats[t * L + lab];
        if (t < T_STEPS - 1) s += transfer[lab * L + target[t + 1]];
    }
    #pragma unroll
    for (int o = 16; o; o >>= 1) s += __shfl_xor_sync(0xffffffffu, s, o);

    __shared__ float red[NT / 32];
    if ((tid & 31) == 0) red[tid >> 5] = s;
    __syncthreads();
    if (tid == 0) {
        float tot = 0.f;
        #pragma unroll
        for (int w = 0; w < NT / 32; w++) tot += red[w];
        g_gold = tot;
    }
}

// ---------------------------------------------------------------------------
// Main persistent kernel: exp-domain forward algorithm
//   a_{t+1}[j] = ( sum_i a_t[i] * E[i][j] ) * exp(emit_{t+1}[j]) * 2^{-d_t}
//   d_t = ilogb(max_i a_t[i]) + 11   (identical in every block -> no sync)
//   K   = sum d_t  (integer, exact)
//   log Z = ln(sum_j a_{T-1}[j]) + K * ln 2
// ---------------------------------------------------------------------------
__global__ void __launch_bounds__(NT, 1)
crf_forward_kernel(const float* __restrict__ feats,
                   const float* __restrict__ transfer,
                   float* __restrict__ out) {
    __shared__ float sE[JB][L];   // 32 KB: E tile, resident for all steps
    __shared__ float sa[L];       // 4 KB : current a vector
    __shared__ float swarp[8];

    const int b    = blockIdx.x;
    const int tid  = threadIdx.x;
    const int w    = tid >> 5;
    const int lane = tid & 31;
    const int jb   = b * JB;

    // Load E tile: sE[jj][i] = exp(transfer[i][jb+jj])  (transfer read ONCE)
    for (int n = tid; n < JB * L; n += NT) {
        int i = n >> 3, jj = n & 7;
        sE[jj][i] = __expf(transfer[i * L + jb + jj]);
    }

    // a_0 = exp(feats[0])
    if (tid < JB) {
        g_a[0][jb + tid] = __expf(feats[jb + tid]);
    }
    __syncthreads();
    if (tid == 0) { __threadfence(); st_release(&g_seq[b], 1); }

    int K = 0;

    for (int t = 0; t < T_STEPS - 1; t++) {
        // Prefetch emission for this warp's column (hides latency behind wait)
        float emit = feats[(t + 1) * L + jb + w];

        // Wait for all chunks of a_t
        if (tid < NB) {
            while (ld_acquire(&g_seq[tid]) < t + 1) { }
        }
        __syncthreads();

        // Load a_t (L2-coherent, bypass possibly-stale L1), compute global max
        const float4* ga4 = (const float4*)g_a[t & 1];
        float4 av = __ldcg(&ga4[tid]);
        ((float4*)sa)[tid] = av;
        float m = fmaxf(fmaxf(av.x, av.y), fmaxf(av.z, av.w));
        #pragma unroll
        for (int o = 16; o; o >>= 1) m = fmaxf(m, __shfl_xor_sync(0xffffffffu, m, o));
        if (lane == 0) swarp[w] = m;
        __syncthreads();   // also publishes sa[] for the mat-vec below

        float maxa = swarp[0];
        #pragma unroll
        for (int q = 1; q < 8; q++) maxa = fmaxf(maxa, swarp[q]);
        int d = ((__float_as_int(maxa) >> 23) & 0xFF) - 127 + 11;
        K += d;

        // Mat-vec: warp w computes s = sum_i a[i] * E[i][jb+w]
        float4 A = make_float4(0.f, 0.f, 0.f, 0.f);
        const float4* e4 = (const float4*)sE[w];
        const float4* a4 = (const float4*)sa;
        #pragma unroll
        for (int k = 0; k < 8; k++) {
            float4 ev = e4[lane + 32 * k];
            float4 aa = a4[lane + 32 * k];
            A.x += ev.x * aa.x; A.y += ev.y * aa.y;
            A.z += ev.z * aa.z; A.w += ev.w * aa.w;
        }
        float s = (A.x + A.y) + (A.z + A.w);
        #pragma unroll
        for (int o = 16; o; o >>= 1) s += __shfl_xor_sync(0xffffffffu, s, o);

        if (lane == 0) {
            float an = s * exp2f(emit * LOG2E_F - (float)d);
            g_a[(t + 1) & 1][jb + w] = an;
        }
        __syncthreads();
        if (tid == 0) { __threadfence(); st_release(&g_seq[b], t + 2); }
    }

    // Finalize: block 0 computes log Z and writes the loss
    if (b == 0) {
        if (tid < NB) {
            while (ld_acquire(&g_seq[tid]) < T_STEPS) { }
        }
        __syncthreads();
        const float4* ga4 = (const float4*)g_a[(T_STEPS - 1) & 1];
        float4 av = __ldcg(&ga4[tid]);
        float s = (av.x + av.y) + (av.z + av.w);
        #pragma unroll
        for (int o = 16; o; o >>= 1) s += __shfl_xor_sync(0xffffffffu, s, o);
        if (lane == 0) swarp[w] = s;
        __syncthreads();
        if (tid == 0) {
            float tot = 0.f;
            #pragma unroll
            for (int q = 0; q < 8; q++) tot += swarp[q];
            double lz = log((double)tot) + (double)K * 0.69314718055994530942;
            out[0] = (float)(lz - (double)g_gold);
        }
    }
}

extern "C" void kernel_launch(void* const* d_in, const int* in_sizes, int n_in,
                              void* d_out, int out_size) {
    const float* feats    = (const float*)d_in[0];   // [2048, 1024] f32
    const float* transfer = (const float*)d_in[1];   // [1024, 1024] f32
    const int*   target   = (const int*)d_in[2];     // [2048] i32
    float* out = (float*)d_out;

    crf_prep_kernel<<<1, NT>>>(feats, transfer, target);
    crf_forward_kernel<<<NB, NT>>>(feats, transfer, out);
}

// round 4
// speedup vs baseline: 1.8645x; 1.8645x over previous
#include <cuda_runtime.h>
#include <math.h>

#define T_STEPS 2048
#define L 1024
#define NB 128          // persistent blocks (<=148 SMs -> all co-resident)
#define JB 8            // columns per block (NB*JB == L)
#define NT 256          // 8 warps; warp w owns column b*JB + w
#define NREP 4          // replicas of the score vector (spread L2 broadcast)
#define LOG2E_F 1.4426950408889634f

// Device scratch (static; no runtime allocation)
__device__ float g_a[2][NREP][L];   // depth-2 ring x 4 replicas (32 KB)
__device__ int   g_seq[NB];         // monotonic per-block flags
__device__ float g_gold;

__device__ __forceinline__ int ld_acquire(const int* p) {
    int v;
    asm volatile("ld.acquire.gpu.global.s32 %0, [%1];" : "=r"(v) : "l"(p) : "memory");
    return v;
}
__device__ __forceinline__ void st_release(int* p, int v) {
    asm volatile("st.release.gpu.global.s32 [%0], %1;" :: "l"(p), "r"(v) : "memory");
}
__device__ __forceinline__ void st_cg(float* p, float v) {
    asm volatile("st.global.cg.f32 [%0], %1;" :: "l"(p), "f"(v) : "memory");
}

// ---------------------------------------------------------------------------
// Prep: reset flags + gold path score (runs before forward every replay)
// ---------------------------------------------------------------------------
__global__ void crf_prep_kernel(const float* __restrict__ feats,
                                const float* __restrict__ transfer,
                                const int*   __restrict__ target) {
    int tid = threadIdx.x;
    if (tid < NB) g_seq[tid] = 0;

    float s = 0.f;
    for (int t = tid; t < T_STEPS; t += NT) {
        int lab = target[t];
        s += feats[t * L + lab];
        if (t < T_STEPS - 1) s += transfer[lab * L + target[t + 1]];
    }
    #pragma unroll
    for (int o = 16; o; o >>= 1) s += __shfl_xor_sync(0xffffffffu, s, o);

    __shared__ float red[NT / 32];
    if ((tid & 31) == 0) red[tid >> 5] = s;
    __syncthreads();
    if (tid == 0) {
        float tot = 0.f;
        #pragma unroll
        for (int w = 0; w < NT / 32; w++) tot += red[w];
        g_gold = tot;
    }
}

// ---------------------------------------------------------------------------
// Persistent forward kernel, exp domain:
//   a_{t+1}[j] = (sum_i a_t[i]*E[i][j]) * exp(emit_{t+1}[j]) * 2^{-d_t}
//   d_t = ilogb(max_i a_t[i]) + 11   (max is order-insensitive -> identical
//                                     in every warp/block, no extra sync)
//   log Z = ln(sum_j a_{T-1}[j]) + (sum_t d_t)*ln2
// Sync: per-block monotonic flags, st.release / ld.acquire (NO threadfence).
// ---------------------------------------------------------------------------
__global__ void __launch_bounds__(NT, 1)
crf_forward_kernel(const float* __restrict__ feats,
                   const float* __restrict__ transfer,
                   float* __restrict__ out) {
    __shared__ float sa[L];      // staged a_t (4 KB)
    __shared__ float sred[8];

    const int b    = blockIdx.x;
    const int tid  = threadIdx.x;
    const int w    = tid >> 5;
    const int lane = tid & 31;
    const int col  = b * JB + w;          // this warp's output column
    const int rep  = b & (NREP - 1);      // which replica this block reads

    // E column in registers: E[k].{x..w} = exp(transfer[i][col]), i=4*lane+128k+c
    float4 E[8];
    #pragma unroll
    for (int k = 0; k < 8; k++) {
        int i = lane * 4 + 128 * k;
        E[k].x = __expf(transfer[(i + 0) * L + col]);
        E[k].y = __expf(transfer[(i + 1) * L + col]);
        E[k].z = __expf(transfer[(i + 2) * L + col]);
        E[k].w = __expf(transfer[(i + 3) * L + col]);
    }

    // a_0 = exp(feats[0]): publish to all replicas, then release flag=1
    if (lane == 0) {
        float a0 = __expf(feats[col]);
        #pragma unroll
        for (int r = 0; r < NREP; r++) st_cg(&g_a[0][r][col], a0);
    }
    __syncthreads();
    if (tid == 0) st_release(&g_seq[b], 1);

    int K = 0;

    for (int t = 0; t < T_STEPS - 1; t++) {
        // off-critical-path: emission factor for this warp's column
        float exp_emit = __expf(__ldg(&feats[(t + 1) * L + col]));

        // warp 0 polls all NB flags (lane q*32+lane), then block barrier
        if (w == 0) {
            #pragma unroll
            for (int q = 0; q < 4; q++) {
                const int* fp = &g_seq[lane + 32 * q];
                while (ld_acquire(fp) < t + 1) { }
            }
        }
        __syncthreads();

        // fetch this thread's 4 entries of a_t from our replica, stage to SMEM
        float4 av = __ldcg(((const float4*)g_a[t & 1][rep]) + tid);
        ((float4*)sa)[tid] = av;
        __syncthreads();

        // mat-vec + full-vector max (max is order-insensitive => identical d)
        float4 A = make_float4(0.f, 0.f, 0.f, 0.f);
        float mx = 0.f;
        #pragma unroll
        for (int k = 0; k < 8; k++) {
            float4 aa = ((const float4*)sa)[lane + 32 * k];
            A.x = fmaf(aa.x, E[k].x, A.x);
            A.y = fmaf(aa.y, E[k].y, A.y);
            A.z = fmaf(aa.z, E[k].z, A.z);
            A.w = fmaf(aa.w, E[k].w, A.w);
            mx = fmaxf(mx, fmaxf(fmaxf(aa.x, aa.y), fmaxf(aa.z, aa.w)));
        }
        float s = (A.x + A.y) + (A.z + A.w);
        #pragma unroll
        for (int o = 16; o; o >>= 1) {
            s  += __shfl_xor_sync(0xffffffffu, s, o);
            mx = fmaxf(mx, __shfl_xor_sync(0xffffffffu, mx, o));
        }

        int d = ((__float_as_int(mx) >> 23) & 0xFF) - 116;   // ilogb(mx)+11
        K += d;

        if (lane == 0) {
            float an = s * exp_emit * __int_as_float((127 - d) << 23); // *2^-d exact
            #pragma unroll
            for (int r = 0; r < NREP; r++) st_cg(&g_a[(t + 1) & 1][r][col], an);
        }
        __syncthreads();                       // all stores done block-wide
        if (tid == 0) st_release(&g_seq[b], t + 2);
    }

    // Finalize: block 0 gathers a_{T-1}, writes the loss
    if (b == 0) {
        if (w == 0) {
            #pragma unroll
            for (int q = 0; q < 4; q++) {
                const int* fp = &g_seq[lane + 32 * q];
                while (ld_acquire(fp) < T_STEPS) { }
            }
        }
        __syncthreads();
        float4 av = __ldcg(((const float4*)g_a[(T_STEPS - 1) & 1][0]) + tid);
        float s = (av.x + av.y) + (av.z + av.w);
        #pragma unroll
        for (int o = 16; o; o >>= 1) s += __shfl_xor_sync(0xffffffffu, s, o);
        if (lane == 0) sred[w] = s;
        __syncthreads();
        if (tid == 0) {
            float tot = 0.f;
            #pragma unroll
            for (int q = 0; q < 8; q++) tot += sred[q];
            double lz = log((double)tot) + (double)K * 0.69314718055994530942;
            out[0] = (float)(lz - (double)g_gold);
        }
    }
}

extern "C" void kernel_launch(void* const* d_in, const int* in_sizes, int n_in,
                              void* d_out, int out_size) {
    const float* feats    = (const float*)d_in[0];   // [2048, 1024] f32
    const float* transfer = (const float*)d_in[1];   // [1024, 1024] f32
    const int*   target   = (const int*)d_in[2];     // [2048] i32
    float* out = (float*)d_out;

    crf_prep_kernel<<<1, NT>>>(feats, transfer, target);
    crf_forward_kernel<<<NB, NT>>>(feats, transfer, out);
}

// round 5
// speedup vs baseline: 2.5542x; 1.3699x over previous
#include <cuda_runtime.h>
#include <math.h>

#define T_STEPS 2048
#define L 1024
#define NB 128          // persistent blocks (<=148 SMs -> all co-resident)
#define JB 8            // columns per block (NB*JB == L)
#define NT 256          // 8 warps; warp w owns column b*JB + w
#define NREP 2          // replicas of the score vector (spread L2 load)
#define POISON_U 0xFFC00000u   // -NaN: sign bit set; real values >= +0

// Static device scratch. Write-once per replay: every word goes
// poison -> final value exactly once (prep re-poisons between replays).
__device__ float g_hist[T_STEPS][NREP][L];   // 16 MB
__device__ float g_gold;

// ---------------------------------------------------------------------------
// helpers: release publish / acquire poll (proven protocol from R4)
// ---------------------------------------------------------------------------
__device__ __forceinline__ float ld_acq(const float* p) {
    float v;
    asm volatile("ld.acquire.gpu.global.f32 %0, [%1];" : "=f"(v) : "l"(p) : "memory");
    return v;
}
__device__ __forceinline__ void st_rel(float* p, float v) {
    asm volatile("st.release.gpu.global.f32 [%0], %1;" :: "l"(p), "f"(v) : "memory");
}

// Poll this thread's 4 words of a_t until none carries the poison sign bit.
// 4 independent acquire loads per round (MLP=4, one L2 trip per round).
__device__ __forceinline__ float4 poll4_acq(const float* p) {
    float4 v;
    for (;;) {
        v.x = ld_acq(p + 0);
        v.y = ld_acq(p + 1);
        v.z = ld_acq(p + 2);
        v.w = ld_acq(p + 3);
        if ((__float_as_int(v.x) | __float_as_int(v.y) |
             __float_as_int(v.z) | __float_as_int(v.w)) >= 0) return v;
    }
}

// ---------------------------------------------------------------------------
// Prep: poison the whole history (16 MB, big grid) + gold path score
// ---------------------------------------------------------------------------
__global__ void crf_prep_kernel(const float* __restrict__ feats,
                                const float* __restrict__ transfer,
                                const int*   __restrict__ target) {
    unsigned idx    = blockIdx.x * blockDim.x + threadIdx.x;
    unsigned stride = gridDim.x * blockDim.x;
    uint4 pz = make_uint4(POISON_U, POISON_U, POISON_U, POISON_U);
    uint4* gh = (uint4*)g_hist;
    for (unsigned n = idx; n < (T_STEPS * NREP * L) / 4; n += stride) gh[n] = pz;

    if (blockIdx.x == 0) {
        int tid = threadIdx.x;
        float s = 0.f;
        for (int t = tid; t < T_STEPS; t += NT) {
            int lab = target[t];
            s += feats[t * L + lab];
            if (t < T_STEPS - 1) s += transfer[lab * L + target[t + 1]];
        }
        #pragma unroll
        for (int o = 16; o; o >>= 1) s += __shfl_xor_sync(0xffffffffu, s, o);
        __shared__ float red[NT / 32];
        if ((tid & 31) == 0) red[tid >> 5] = s;
        __syncthreads();
        if (tid == 0) {
            float tot = 0.f;
            #pragma unroll
            for (int w = 0; w < NT / 32; w++) tot += red[w];
            g_gold = tot;
        }
    }
}

// ---------------------------------------------------------------------------
// Persistent forward kernel, exp domain:
//   a_{t+1}[j] = (sum_i a_t[i]*E[i][j]) * exp(emit_{t+1}[j]) * 2^{-d_t}
//   d_t = ilogb(max_i a_t[i]) + 11   (bitwise-identical in every warp/block)
//   log Z = ln(sum_j a_{T-1}[j]) + (sum_t d_t)*ln2
// Sync: data IS the flag. Write-once slots, st.release publish,
//       ld.acquire polls — one cross-SM round trip per step.
// ---------------------------------------------------------------------------
__global__ void __launch_bounds__(NT, 1)
crf_forward_kernel(const float* __restrict__ feats,
                   const float* __restrict__ transfer,
                   float* __restrict__ out) {
    __shared__ float sa[2][L];    // double-buffered staged a_t (8 KB)
    __shared__ float sred[8];

    const int b    = blockIdx.x;
    const int tid  = threadIdx.x;
    const int w    = tid >> 5;
    const int lane = tid & 31;
    const int col  = b * JB + w;           // this warp's output column
    const int rep  = b & (NREP - 1);       // replica this block reads

    // E column in registers: E[k].{x..w} = exp(transfer[i][col]), i=4*lane+128k+c
    float4 E[8];
    #pragma unroll
    for (int k = 0; k < 8; k++) {
        int i = lane * 4 + 128 * k;
        E[k].x = __expf(transfer[(i + 0) * L + col]);
        E[k].y = __expf(transfer[(i + 1) * L + col]);
        E[k].z = __expf(transfer[(i + 2) * L + col]);
        E[k].w = __expf(transfer[(i + 3) * L + col]);
    }

    // a_0 = exp(feats[0]): publish once per replica (release)
    if (lane == 0) {
        float a0 = __expf(feats[col]);
        #pragma unroll
        for (int r = 0; r < NREP; r++) st_rel(&g_hist[0][r][col], a0);
    }

    int K = 0;

    for (int t = 0; t < T_STEPS - 1; t++) {
        // independent of the poll: emission factor for this warp's column
        float exp_emit = __expf(__ldg(&feats[(t + 1) * L + col]));

        // acquire-poll this thread's 4 entries of a_t (data-as-flag)
        float4 av = poll4_acq(&g_hist[t][rep][tid * 4]);
        ((float4*)sa[t & 1])[tid] = av;
        __syncthreads();     // the ONLY barrier per step (double buffer)

        // mat-vec + full-vector max (order-insensitive => identical d)
        const float4* a4 = (const float4*)sa[t & 1];
        float4 A = make_float4(0.f, 0.f, 0.f, 0.f);
        float mx = 0.f;
        #pragma unroll
        for (int k = 0; k < 8; k++) {
            float4 aa = a4[lane + 32 * k];
            A.x = fmaf(aa.x, E[k].x, A.x);
            A.y = fmaf(aa.y, E[k].y, A.y);
            A.z = fmaf(aa.z, E[k].z, A.z);
            A.w = fmaf(aa.w, E[k].w, A.w);
            mx = fmaxf(mx, fmaxf(fmaxf(aa.x, aa.y), fmaxf(aa.z, aa.w)));
        }
        float s = (A.x + A.y) + (A.z + A.w);
        #pragma unroll
        for (int o = 16; o; o >>= 1) {
            s  += __shfl_xor_sync(0xffffffffu, s, o);
            mx = fmaxf(mx, __shfl_xor_sync(0xffffffffu, mx, o));
        }

        int d = ((__float_as_int(mx) >> 23) & 0xFF) - 116;   // ilogb(mx)+11
        K += d;

        if (lane == 0) {
            float an = s * exp_emit * __int_as_float((127 - d) << 23); // *2^-d exact
            #pragma unroll
            for (int r = 0; r < NREP; r++) st_rel(&g_hist[t + 1][r][col], an);
        }
    }

    // Finalize: block 0 gathers a_{T-1} (write-once, acquire-poll) -> loss
    if (b == 0) {
        float4 av = poll4_acq(&g_hist[T_STEPS - 1][0][tid * 4]);
        float s = (av.x + av.y) + (av.z + av.w);
        #pragma unroll
        for (int o = 16; o; o >>= 1) s += __shfl_xor_sync(0xffffffffu, s, o);
        if (lane == 0) sred[w] = s;
        __syncthreads();
        if (tid == 0) {
            float tot = 0.f;
            #pragma unroll
            for (int q = 0; q < 8; q++) tot += sred[q];
            double lz = log((double)tot) + (double)K * 0.69314718055994530942;
            out[0] = (float)(lz - (double)g_gold);
        }
    }
}

extern "C" void kernel_launch(void* const* d_in, const int* in_sizes, int n_in,
                              void* d_out, int out_size) {
    const float* feats    = (const float*)d_in[0];   // [2048, 1024] f32
    const float* transfer = (const float*)d_in[1];   // [1024, 1024] f32
    const int*   target   = (const int*)d_in[2];     // [2048] i32
    float* out = (float*)d_out;

    crf_prep_kernel<<<2048, NT>>>(feats, transfer, target);
    crf_forward_kernel<<<NB, NT>>>(feats, transfer, out);
}